// round 2
// baseline (speedup 1.0000x reference)
#include <cuda_runtime.h>
#include <math.h>

// Problem constants
constexpr int NB = 4;      // batch
constexpr int NT = 2048;   // seq len
constexpr int NK = 1024;   // model dim
constexpr int NH = 16;     // heads
constexpr int ND = 64;     // head dim
constexpr int MROWS = NB * NT;  // 8192

// Scratch (allocation-free rule: __device__ globals)
__device__ float g_q[NB * NH * NT * ND];    // [B,H,T,HD], pre-scaled
__device__ float g_k[NB * NH * NT * ND];    // [B,H,T,HD], pre-scaled
__device__ float g_v[NB * NH * NT * ND];    // [B,H,T,HD]
__device__ float g_ctx[MROWS * NK];         // [B*T, K] attention output

// ---------------------------------------------------------------------------
// SGEMM: C = A(MxK) @ W^T  (W is [N,K] row-major, torch Linear convention)
// mode 0: scatter to [B,H,T,HD] layout, multiply by `scale`
// mode 1: write [M,N] row-major, add bias[n]
// ---------------------------------------------------------------------------
constexpr int BM = 64, BN = 64, BKT = 16;

__global__ __launch_bounds__(256)
void gemm_kernel(const float* __restrict__ A, const float* __restrict__ W,
                 const float* __restrict__ bias, float* __restrict__ C,
                 float scale, int mode)
{
    __shared__ float As[BKT][BM + 1];
    __shared__ float Bs[BKT][BN + 1];

    const int tid = threadIdx.x;
    const int tx = tid & 15;          // 0..15 -> N direction
    const int ty = tid >> 4;          // 0..15 -> M direction
    const int row0 = blockIdx.y * BM;
    const int col0 = blockIdx.x * BN;

    float acc[4][4] = {};

    for (int k0 = 0; k0 < NK; k0 += BKT) {
        // Load tiles (coalesced 64B segments), transposed into [k][m]/[k][n]
        #pragma unroll
        for (int i = 0; i < 4; i++) {
            int e = tid + i * 256;
            int m = e >> 4;       // 0..63
            int kk = e & 15;      // 0..15
            As[kk][m] = A[(size_t)(row0 + m) * NK + k0 + kk];
            Bs[kk][m] = W[(size_t)(col0 + m) * NK + k0 + kk];
        }
        __syncthreads();

        #pragma unroll
        for (int kk = 0; kk < BKT; kk++) {
            float a[4], b[4];
            #pragma unroll
            for (int i = 0; i < 4; i++) a[i] = As[kk][ty * 4 + i];
            #pragma unroll
            for (int j = 0; j < 4; j++) b[j] = Bs[kk][tx * 4 + j];
            #pragma unroll
            for (int i = 0; i < 4; i++)
                #pragma unroll
                for (int j = 0; j < 4; j++)
                    acc[i][j] += a[i] * b[j];
        }
        __syncthreads();
    }

    if (mode == 0) {
        // scatter into [B,H,T,HD] with scale
        #pragma unroll
        for (int i = 0; i < 4; i++) {
            int m = row0 + ty * 4 + i;
            int bb = m / NT, t = m % NT;
            #pragma unroll
            for (int j = 0; j < 4; j++) {
                int n = col0 + tx * 4 + j;
                int h = n >> 6, d = n & 63;
                C[(((size_t)bb * NH + h) * NT + t) * ND + d] = acc[i][j] * scale;
            }
        }
    } else {
        #pragma unroll
        for (int i = 0; i < 4; i++) {
            int m = row0 + ty * 4 + i;
            #pragma unroll
            for (int j = 0; j < 4; j++) {
                int n = col0 + tx * 4 + j;
                C[(size_t)m * NK + n] = acc[i][j] + bias[n];
            }
        }
    }
}

// ---------------------------------------------------------------------------
// Flash-style attention, fp32. One block = (b, h, 64-query tile).
// Online softmax over 32 key tiles of 64. Matches reference masking:
// masked scores get -10000 added (NOT -inf).
// ---------------------------------------------------------------------------
constexpr int LDS_STRIDE = 65;
constexpr int ATTN_SMEM_FLOATS = 4 * 64 * LDS_STRIDE + 3 * 64;
constexpr int ATTN_SMEM_BYTES = ATTN_SMEM_FLOATS * 4;

__global__ __launch_bounds__(256)
void attn_kernel(const float* __restrict__ Q, const float* __restrict__ Kp,
                 const float* __restrict__ Vp, const int* __restrict__ lengths,
                 float* __restrict__ ctx)
{
    extern __shared__ float sm[];
    float* Qs = sm;                        // 64 x 65
    float* Ks = Qs + 64 * LDS_STRIDE;      // 64 x 65
    float* Vs = Ks + 64 * LDS_STRIDE;      // 64 x 65
    float* Ss = Vs + 64 * LDS_STRIDE;      // 64 x 65
    float* rmax = Ss + 64 * LDS_STRIDE;    // 64
    float* rsum = rmax + 64;               // 64
    float* rcorr = rsum + 64;              // 64

    const int b = blockIdx.z, h = blockIdx.y;
    const int t0 = blockIdx.x * 64;
    const int tid = threadIdx.x;
    const int tx = tid & 15;   // key-col / dim-col group
    const int ty = tid >> 4;   // query-row group

    const size_t headbase = ((size_t)b * NH + h) * NT * ND;
    const float* Qb = Q + headbase + (size_t)t0 * ND;
    const float* Kb = Kp + headbase;
    const float* Vb = Vp + headbase;
    const int len = lengths[b];   // int32 (JAX default x64-disabled => int32 array)

    // Load Q tile (coalesced)
    #pragma unroll
    for (int i = 0; i < 16; i++) {
        int e = tid + i * 256;
        int r = e >> 6, d = e & 63;
        Qs[r * LDS_STRIDE + d] = Qb[r * ND + d];
    }
    if (tid < 64) { rmax[tid] = -1e30f; rsum[tid] = 0.0f; }

    float o[4][4] = {};
    __syncthreads();

    for (int kt = 0; kt < NT / 64; kt++) {
        const float* Kt = Kb + (size_t)kt * 64 * ND;
        const float* Vt = Vb + (size_t)kt * 64 * ND;
        #pragma unroll
        for (int i = 0; i < 16; i++) {
            int e = tid + i * 256;
            int r = e >> 6, d = e & 63;
            Ks[r * LDS_STRIDE + d] = Kt[r * ND + d];
            Vs[r * LDS_STRIDE + d] = Vt[r * ND + d];
        }
        __syncthreads();

        // S = Q . K^T   (each thread: 4 queries x 4 keys)
        float s[4][4] = {};
        #pragma unroll 8
        for (int d = 0; d < 64; d++) {
            float a[4], bb[4];
            #pragma unroll
            for (int i = 0; i < 4; i++) a[i] = Qs[(ty * 4 + i) * LDS_STRIDE + d];
            #pragma unroll
            for (int j = 0; j < 4; j++) bb[j] = Ks[(tx * 4 + j) * LDS_STRIDE + d];
            #pragma unroll
            for (int i = 0; i < 4; i++)
                #pragma unroll
                for (int j = 0; j < 4; j++)
                    s[i][j] += a[i] * bb[j];
        }
        // mask (reference semantics: + (1-valid) * -10000) and stage to smem
        #pragma unroll
        for (int j = 0; j < 4; j++) {
            int kg = kt * 64 + tx * 4 + j;
            float pen = (kg < len) ? 0.0f : -10000.0f;
            #pragma unroll
            for (int i = 0; i < 4; i++)
                Ss[(ty * 4 + i) * LDS_STRIDE + tx * 4 + j] = s[i][j] + pen;
        }
        __syncthreads();

        // Online softmax row stats (one thread per query row)
        if (tid < 64) {
            float* srow = &Ss[tid * LDS_STRIDE];
            float mold = rmax[tid];
            float mx = mold;
            #pragma unroll 8
            for (int c = 0; c < 64; c++) mx = fmaxf(mx, srow[c]);
            float corr = __expf(mold - mx);
            float sum = 0.0f;
            #pragma unroll 8
            for (int c = 0; c < 64; c++) {
                float p = __expf(srow[c] - mx);
                srow[c] = p;
                sum += p;
            }
            rsum[tid] = rsum[tid] * corr + sum;
            rmax[tid] = mx;
            rcorr[tid] = corr;
        }
        __syncthreads();

        // Rescale O and accumulate P @ V
        float c_[4];
        #pragma unroll
        for (int i = 0; i < 4; i++) c_[i] = rcorr[ty * 4 + i];
        #pragma unroll
        for (int i = 0; i < 4; i++)
            #pragma unroll
            for (int j = 0; j < 4; j++)
                o[i][j] *= c_[i];

        #pragma unroll 8
        for (int kk = 0; kk < 64; kk++) {
            float p[4], vv[4];
            #pragma unroll
            for (int i = 0; i < 4; i++) p[i] = Ss[(ty * 4 + i) * LDS_STRIDE + kk];
            #pragma unroll
            for (int j = 0; j < 4; j++) vv[j] = Vs[kk * LDS_STRIDE + tx * 4 + j];
            #pragma unroll
            for (int i = 0; i < 4; i++)
                #pragma unroll
                for (int j = 0; j < 4; j++)
                    o[i][j] += p[i] * vv[j];
        }
        __syncthreads();
    }

    // Normalize and write to [B*T, K] context buffer (col = h*64 + d)
    #pragma unroll
    for (int i = 0; i < 4; i++) {
        int q = ty * 4 + i;
        float inv = 1.0f / rsum[q];
        size_t rowbase = ((size_t)b * NT + t0 + q) * NK + h * ND;
        #pragma unroll
        for (int j = 0; j < 4; j++)
            ctx[rowbase + tx * 4 + j] = o[i][j] * inv;
    }
}

// ---------------------------------------------------------------------------
extern "C" void kernel_launch(void* const* d_in, const int* in_sizes, int n_in,
                              void* d_out, int out_size)
{
    const float* x0  = (const float*)d_in[0];
    const int* lens  = (const int*)d_in[1];   // JAX default x64-disabled: int32
    const float* Wq  = (const float*)d_in[2];
    const float* Wk  = (const float*)d_in[3];
    const float* Wv  = (const float*)d_in[4];
    const float* Wu  = (const float*)d_in[5];
    const float* bu  = (const float*)d_in[6];
    float* out       = (float*)d_out;

    float* dq;  cudaGetSymbolAddress((void**)&dq,  g_q);
    float* dk;  cudaGetSymbolAddress((void**)&dk,  g_k);
    float* dv;  cudaGetSymbolAddress((void**)&dv,  g_v);
    float* dctx; cudaGetSymbolAddress((void**)&dctx, g_ctx);

    cudaFuncSetAttribute(attn_kernel, cudaFuncAttributeMaxDynamicSharedMemorySize,
                         ATTN_SMEM_BYTES);

    const float qk_scale = 0.35355339059327373f;  // 64^(-0.25)

    dim3 ggrid(NK / BN, MROWS / BM);   // (16, 128)
    gemm_kernel<<<ggrid, 256>>>(x0, Wq, nullptr, dq, qk_scale, 0);
    gemm_kernel<<<ggrid, 256>>>(x0, Wk, nullptr, dk, qk_scale, 0);
    gemm_kernel<<<ggrid, 256>>>(x0, Wv, nullptr, dv, 1.0f, 0);

    dim3 agrid(NT / 64, NH, NB);       // (32, 16, 4)
    attn_kernel<<<agrid, 256, ATTN_SMEM_BYTES>>>(dq, dk, dv, lens, dctx);

    gemm_kernel<<<ggrid, 256>>>(dctx, Wu, bu, out, 1.0f, 1);
}

// round 3
// speedup vs baseline: 2.5522x; 2.5522x over previous
#include <cuda_runtime.h>
#include <cstdint>
#include <math.h>

// Problem constants
constexpr int NB = 4;      // batch
constexpr int NT = 2048;   // seq len
constexpr int NK = 1024;   // model dim
constexpr int NH = 16;     // heads
constexpr int ND = 64;     // head dim
constexpr int MROWS = NB * NT;  // 8192

// Scratch (allocation-free rule: __device__ globals)
__device__ float g_q[NB * NH * NT * ND];    // [B,H,T,HD], pre-scaled
__device__ float g_k[NB * NH * NT * ND];    // [B,H,T,HD], pre-scaled
__device__ float g_v[NB * NH * NT * ND];    // [B,H,T,HD]
__device__ float g_ctx[MROWS * NK];         // [B*T, K] attention output

// ---------------------------------------------------------------------------
// tf32 helpers
// ---------------------------------------------------------------------------
__device__ __forceinline__ uint32_t f2tf(float f) {
    uint32_t u;
    asm("cvt.rna.tf32.f32 %0, %1;" : "=r"(u) : "f"(f));
    return u;
}

__device__ __forceinline__ void mma_tf32(float* c, const uint32_t* a, const uint32_t* b) {
    asm volatile(
        "mma.sync.aligned.m16n8k8.row.col.f32.tf32.tf32.f32 "
        "{%0,%1,%2,%3}, {%4,%5,%6,%7}, {%8,%9}, {%0,%1,%2,%3};"
        : "+f"(c[0]), "+f"(c[1]), "+f"(c[2]), "+f"(c[3])
        : "r"(a[0]), "r"(a[1]), "r"(a[2]), "r"(a[3]), "r"(b[0]), "r"(b[1]));
}

// ---------------------------------------------------------------------------
// tf32 GEMM: C = A(MxK) @ W^T   (W is [N,K] row-major)
// Block 128x128, BK=16, 8 warps (2x4), each warp 64x32.
// mode 0: scatter to [B,H,T,HD], multiply by scale
// mode 1: write [M,N] row-major + bias[n]
// ---------------------------------------------------------------------------
constexpr int GST = 20;  // smem row stride (conflict-free frag reads)

__global__ __launch_bounds__(256)
void gemm_tf32(const float* __restrict__ A, const float* __restrict__ W,
               const float* __restrict__ bias, float* __restrict__ C,
               float scale, int mode)
{
    __shared__ uint32_t As[128 * GST];
    __shared__ uint32_t Ws[128 * GST];

    const int tid = threadIdx.x;
    const int warp = tid >> 5, lane = tid & 31;
    const int g = lane >> 2, i4 = lane & 3;
    const int mw = warp >> 2;   // 0..1 -> 64-row slab
    const int nw = warp & 3;    // 0..3 -> 32-col slab
    const int row0 = blockIdx.y * 128;
    const int col0 = blockIdx.x * 128;

    const int lr = tid >> 1;          // 0..127  (load row)
    const int lc = (tid & 1) * 8;     // 0 or 8  (load col base)

    float acc[4][4][4] = {};  // [mfrag][nfrag][4]

    for (int k0 = 0; k0 < NK; k0 += 16) {
        // load & convert A,W tiles
        {
            const float* pa = &A[(size_t)(row0 + lr) * NK + k0 + lc];
            float4 v0 = *(const float4*)pa;
            float4 v1 = *(const float4*)(pa + 4);
            uint32_t* d = &As[lr * GST + lc];
            d[0]=f2tf(v0.x); d[1]=f2tf(v0.y); d[2]=f2tf(v0.z); d[3]=f2tf(v0.w);
            d[4]=f2tf(v1.x); d[5]=f2tf(v1.y); d[6]=f2tf(v1.z); d[7]=f2tf(v1.w);
        }
        {
            const float* pw = &W[(size_t)(col0 + lr) * NK + k0 + lc];
            float4 v0 = *(const float4*)pw;
            float4 v1 = *(const float4*)(pw + 4);
            uint32_t* d = &Ws[lr * GST + lc];
            d[0]=f2tf(v0.x); d[1]=f2tf(v0.y); d[2]=f2tf(v0.z); d[3]=f2tf(v0.w);
            d[4]=f2tf(v1.x); d[5]=f2tf(v1.y); d[6]=f2tf(v1.z); d[7]=f2tf(v1.w);
        }
        __syncthreads();

        #pragma unroll
        for (int kk = 0; kk < 16; kk += 8) {
            uint32_t af[4][4], bf[4][2];
            #pragma unroll
            for (int mf = 0; mf < 4; mf++) {
                int mr = mw * 64 + mf * 16;
                af[mf][0] = As[(mr + g    ) * GST + kk + i4];
                af[mf][1] = As[(mr + g + 8) * GST + kk + i4];
                af[mf][2] = As[(mr + g    ) * GST + kk + i4 + 4];
                af[mf][3] = As[(mr + g + 8) * GST + kk + i4 + 4];
            }
            #pragma unroll
            for (int nf = 0; nf < 4; nf++) {
                int nc = nw * 32 + nf * 8;
                bf[nf][0] = Ws[(nc + g) * GST + kk + i4];
                bf[nf][1] = Ws[(nc + g) * GST + kk + i4 + 4];
            }
            #pragma unroll
            for (int mf = 0; mf < 4; mf++)
                #pragma unroll
                for (int nf = 0; nf < 4; nf++)
                    mma_tf32(acc[mf][nf], af[mf], bf[nf]);
        }
        __syncthreads();
    }

    // epilogue
    #pragma unroll
    for (int mf = 0; mf < 4; mf++) {
        int r_lo = row0 + mw * 64 + mf * 16 + g;
        int r_hi = r_lo + 8;
        #pragma unroll
        for (int nf = 0; nf < 4; nf++) {
            int c0c = col0 + nw * 32 + nf * 8 + 2 * i4;
            if (mode == 0) {
                #pragma unroll
                for (int e = 0; e < 4; e++) {
                    int m = (e >= 2) ? r_hi : r_lo;
                    int n = c0c + (e & 1);
                    int bb = m >> 11, t = m & (NT - 1);   // NT=2048
                    int h = n >> 6, d = n & 63;
                    C[(((size_t)bb * NH + h) * NT + t) * ND + d] = acc[mf][nf][e] * scale;
                }
            } else {
                *(float2*)&C[(size_t)r_lo * NK + c0c] =
                    make_float2(acc[mf][nf][0] + bias[c0c], acc[mf][nf][1] + bias[c0c + 1]);
                *(float2*)&C[(size_t)r_hi * NK + c0c] =
                    make_float2(acc[mf][nf][2] + bias[c0c], acc[mf][nf][3] + bias[c0c + 1]);
            }
        }
    }
}

// ---------------------------------------------------------------------------
// Flash attention with tf32 mma. One block = (b, h, 64-query tile).
// 8 warps in 4x2 grid: each warp owns a 16x32 slab of the 64x64 S/O tiles.
// ---------------------------------------------------------------------------
constexpr int AST = 68;  // smem row stride (uint32), conflict-free frag reads
constexpr int ATTN_SMEM_BYTES = (4 * 64 * AST + 3 * 64) * 4;

__global__ __launch_bounds__(256)
void attn_tf32(const float* __restrict__ Q, const float* __restrict__ Kp,
               const float* __restrict__ Vp, const int* __restrict__ lengths,
               float* __restrict__ ctx)
{
    extern __shared__ uint32_t smu[];
    uint32_t* Qs = smu;
    uint32_t* Ks = Qs + 64 * AST;
    uint32_t* Vs = Ks + 64 * AST;
    uint32_t* Ss = Vs + 64 * AST;   // S scores (float bits), then P (tf32 bits)
    float* rmax  = (float*)(Ss + 64 * AST);
    float* rsum  = rmax + 64;
    float* rcorr = rsum + 64;

    const int b = blockIdx.z, h = blockIdx.y;
    const int t0 = blockIdx.x * 64;
    const int tid = threadIdx.x;
    const int warp = tid >> 5, lane = tid & 31;
    const int g = lane >> 2, i4 = lane & 3;
    const int mw = warp >> 1;        // 0..3 -> 16-row slab
    const int nw = warp & 1;         // 0..1 -> 32-col slab
    const int m0 = mw * 16;

    const size_t headbase = ((size_t)b * NH + h) * (size_t)NT * ND;
    const float* Qb = Q + headbase + (size_t)t0 * ND;
    const float* Kb = Kp + headbase;
    const float* Vb = Vp + headbase;
    const int len = lengths[b];

    const int lrow = tid >> 2;       // 0..63 (tile load row)
    const int lseg = (tid & 3) * 16; // col base, 16 cols per thread

    // Load+convert Q tile
    #pragma unroll
    for (int s = 0; s < 4; s++) {
        float4 v = *(const float4*)&Qb[lrow * ND + lseg + s * 4];
        uint32_t* d = &Qs[lrow * AST + lseg + s * 4];
        d[0]=f2tf(v.x); d[1]=f2tf(v.y); d[2]=f2tf(v.z); d[3]=f2tf(v.w);
    }
    if (tid < 64) { rmax[tid] = -1e30f; rsum[tid] = 0.0f; }

    float o[4][4] = {};   // [nfrag][4]

    __syncthreads();

    for (int kt = 0; kt < NT / 64; kt++) {
        const float* Kt = Kb + (size_t)kt * 64 * ND;
        const float* Vt = Vb + (size_t)kt * 64 * ND;
        #pragma unroll
        for (int s = 0; s < 4; s++) {
            float4 vk = *(const float4*)&Kt[lrow * ND + lseg + s * 4];
            float4 vv = *(const float4*)&Vt[lrow * ND + lseg + s * 4];
            uint32_t* dk = &Ks[lrow * AST + lseg + s * 4];
            uint32_t* dv = &Vs[lrow * AST + lseg + s * 4];
            dk[0]=f2tf(vk.x); dk[1]=f2tf(vk.y); dk[2]=f2tf(vk.z); dk[3]=f2tf(vk.w);
            dv[0]=f2tf(vv.x); dv[1]=f2tf(vv.y); dv[2]=f2tf(vv.z); dv[3]=f2tf(vv.w);
        }
        __syncthreads();

        // ---- S = Q . K^T (mma) ----
        float sc[4][4] = {};
        #pragma unroll
        for (int kk = 0; kk < 64; kk += 8) {
            uint32_t af[4] = {
                Qs[(m0 + g    ) * AST + kk + i4],
                Qs[(m0 + g + 8) * AST + kk + i4],
                Qs[(m0 + g    ) * AST + kk + i4 + 4],
                Qs[(m0 + g + 8) * AST + kk + i4 + 4]
            };
            #pragma unroll
            for (int nf = 0; nf < 4; nf++) {
                int nc = nw * 32 + nf * 8;
                uint32_t bf[2] = {
                    Ks[(nc + g) * AST + kk + i4],
                    Ks[(nc + g) * AST + kk + i4 + 4]
                };
                mma_tf32(sc[nf], af, bf);
            }
        }
        // stage S to smem (float bits)
        #pragma unroll
        for (int nf = 0; nf < 4; nf++) {
            int nc = nw * 32 + nf * 8 + 2 * i4;
            Ss[(m0 + g    ) * AST + nc    ] = __float_as_uint(sc[nf][0]);
            Ss[(m0 + g    ) * AST + nc + 1] = __float_as_uint(sc[nf][1]);
            Ss[(m0 + g + 8) * AST + nc    ] = __float_as_uint(sc[nf][2]);
            Ss[(m0 + g + 8) * AST + nc + 1] = __float_as_uint(sc[nf][3]);
        }
        __syncthreads();

        // ---- online softmax: 4 threads per row ----
        {
            const int row = tid >> 2, part = tid & 3;
            const int cb = part * 16;
            float vals[16];
            float mold = rmax[row];
            float mx = mold;
            #pragma unroll
            for (int c = 0; c < 16; c++) {
                int cg = kt * 64 + cb + c;
                float v = __uint_as_float(Ss[row * AST + cb + c]);
                v += (cg < len) ? 0.0f : -10000.0f;
                vals[c] = v;
                mx = fmaxf(mx, v);
            }
            mx = fmaxf(mx, __shfl_xor_sync(0xffffffffu, mx, 1));
            mx = fmaxf(mx, __shfl_xor_sync(0xffffffffu, mx, 2));
            float sum = 0.0f;
            #pragma unroll
            for (int c = 0; c < 16; c++) {
                float p = __expf(vals[c] - mx);
                sum += p;
                Ss[row * AST + cb + c] = f2tf(p);   // P as tf32 bits
            }
            sum += __shfl_xor_sync(0xffffffffu, sum, 1);
            sum += __shfl_xor_sync(0xffffffffu, sum, 2);
            if (part == 0) {
                float corr = __expf(mold - mx);
                rsum[row] = rsum[row] * corr + sum;
                rmax[row] = mx;
                rcorr[row] = corr;
            }
        }
        __syncthreads();

        // ---- O = O*corr + P . V (mma) ----
        {
            float c_lo = rcorr[m0 + g], c_hi = rcorr[m0 + g + 8];
            #pragma unroll
            for (int nf = 0; nf < 4; nf++) {
                o[nf][0] *= c_lo; o[nf][1] *= c_lo;
                o[nf][2] *= c_hi; o[nf][3] *= c_hi;
            }
        }
        #pragma unroll
        for (int kk = 0; kk < 64; kk += 8) {
            uint32_t af[4] = {
                Ss[(m0 + g    ) * AST + kk + i4],
                Ss[(m0 + g + 8) * AST + kk + i4],
                Ss[(m0 + g    ) * AST + kk + i4 + 4],
                Ss[(m0 + g + 8) * AST + kk + i4 + 4]
            };
            #pragma unroll
            for (int nf = 0; nf < 4; nf++) {
                int nc = nw * 32 + nf * 8;
                uint32_t bf[2] = {
                    Vs[(kk + i4    ) * AST + nc + g],
                    Vs[(kk + i4 + 4) * AST + nc + g]
                };
                mma_tf32(o[nf], af, bf);
            }
        }
        __syncthreads();
    }

    // normalize + write ctx [B*T, K], col = h*64 + n
    {
        float inv_lo = 1.0f / rsum[m0 + g];
        float inv_hi = 1.0f / rsum[m0 + g + 8];
        size_t rb_lo = ((size_t)b * NT + t0 + m0 + g    ) * NK + h * 64;
        size_t rb_hi = ((size_t)b * NT + t0 + m0 + g + 8) * NK + h * 64;
        #pragma unroll
        for (int nf = 0; nf < 4; nf++) {
            int nc = nw * 32 + nf * 8 + 2 * i4;
            *(float2*)&ctx[rb_lo + nc] = make_float2(o[nf][0] * inv_lo, o[nf][1] * inv_lo);
            *(float2*)&ctx[rb_hi + nc] = make_float2(o[nf][2] * inv_hi, o[nf][3] * inv_hi);
        }
    }
}

// ---------------------------------------------------------------------------
extern "C" void kernel_launch(void* const* d_in, const int* in_sizes, int n_in,
                              void* d_out, int out_size)
{
    const float* x0  = (const float*)d_in[0];
    const int* lens  = (const int*)d_in[1];
    const float* Wq  = (const float*)d_in[2];
    const float* Wk  = (const float*)d_in[3];
    const float* Wv  = (const float*)d_in[4];
    const float* Wu  = (const float*)d_in[5];
    const float* bu  = (const float*)d_in[6];
    float* out       = (float*)d_out;

    float* dq;   cudaGetSymbolAddress((void**)&dq,  g_q);
    float* dk;   cudaGetSymbolAddress((void**)&dk,  g_k);
    float* dv;   cudaGetSymbolAddress((void**)&dv,  g_v);
    float* dctx; cudaGetSymbolAddress((void**)&dctx, g_ctx);

    cudaFuncSetAttribute(attn_tf32, cudaFuncAttributeMaxDynamicSharedMemorySize,
                         ATTN_SMEM_BYTES);

    const float qk_scale = 0.35355339059327373f;  // 64^(-0.25)

    dim3 ggrid(NK / 128, MROWS / 128);   // (8, 64)
    gemm_tf32<<<ggrid, 256>>>(x0, Wq, nullptr, dq, qk_scale, 0);
    gemm_tf32<<<ggrid, 256>>>(x0, Wk, nullptr, dk, qk_scale, 0);
    gemm_tf32<<<ggrid, 256>>>(x0, Wv, nullptr, dv, 1.0f, 0);

    dim3 agrid(NT / 64, NH, NB);         // (32, 16, 4)
    attn_tf32<<<agrid, 256, ATTN_SMEM_BYTES>>>(dq, dk, dv, lens, dctx);

    gemm_tf32<<<ggrid, 256>>>(dctx, Wu, bu, out, 1.0f, 1);
}